// round 12
// baseline (speedup 1.0000x reference)
#include <cuda_runtime.h>
#include <math.h>

// ---------------------------------------------------------------------------
// BalancedFrequencyAttention, collapsed form (see R2 derivation):
//   gap[b,c] = sum_{h,n} x[b,c,h,n] * w(h,n)
//   w(h,n)   = c0 + [h>=80] * (0.4/48000) * g_{(h-80)%3}(n),  period-12 in n
//   att      = sigmoid(gap @ w1^T @ w2^T);  out = x * att[:,:,None,None]
//
// R11: reduce reverted to the proven R8/R9 strided constant-register-weight
// form (R10 contiguous-stripe experiment regressed; theory falsified).
// Scale widened to 4 float4/thread on an exact flat grid (24000 x 1024,
// zero predicates), all loads issued before the PDL sync.
// ---------------------------------------------------------------------------

#define N_CH        1024      // B*C
#define Q_PER_CH    24000     // 200*480/4 float4 per channel
#define BLKS_PER_CH 5
#define TOTAL_Q4    (N_CH * Q_PER_CH)        // 24,576,000 = 24000 * 1024

__device__ float d_part[N_CH * BLKS_PER_CH];
__device__ float d_att[N_CH];

// ---- Kernel 1: weighted reduction, constant-register weights (R8 form) -------
__global__ __launch_bounds__(256, 8) void reduce_kernel(const float4* __restrict__ x) {
    const float c0  = 8.838834764831843e-06f;   // 0.6/sqrt(2)/48000
    const float inv = 8.333333333333334e-06f;   // 0.4/48000
    const float PI  = 3.14159265358979323846f;

    const int blk = blockIdx.x;
    const int ch  = blk / BLKS_PER_CH;
    const int s   = blk - ch * BLKS_PER_CH;

    const int t    = threadIdx.x;
    const int c4   = t & 127;          // float4 column (0..119 active)
    const int r    = t >> 7;           // row-within-pair (0/1)
    const bool act = (c4 < 120);

    // Per-thread constant weight (computed once).
    float4 w = make_float4(c0, c0, c0, c0);
    if (s >= 2) {
        const int k  = s - 2;
        const int n0 = c4 << 2;
        float g[4];
        #pragma unroll
        for (int e = 0; e < 4; e++) {
            float a = (float)(2 * ((n0 + e) % 12) + 1);
            float gv;
            if (k == 0)      gv = cosf(a * (PI / 12.f)) + cosf(a * (PI / 3.f));
            else if (k == 1) gv = cosf(a * (PI / 6.f))  + cosf(a * (5.f * PI / 12.f));
            else             gv = cosf(a * (PI / 4.f));
            g[e] = c0 + inv * gv;
        }
        w = make_float4(g[0], g[1], g[2], g[3]);
    }

    size_t base; int stride;
    if (s < 2) {                           // low: contiguous rows 40s .. 40s+39
        base   = (size_t)ch * Q_PER_CH + (size_t)(40 * s + r) * 120 + c4;
        stride = 240;                      // 2 rows
    } else {                               // high class k: rows 80+k+3m
        base   = (size_t)ch * Q_PER_CH + (size_t)(80 + (s - 2) + 3 * r) * 120 + c4;
        stride = 720;                      // 2 strided rows (6 physical rows)
    }

    float acc0 = 0.f, acc1 = 0.f;
    if (act) {
        const float4* p = x + base;
        #pragma unroll 5
        for (int i = 0; i < 20; i++) {
            float4 v = __ldcs(p);
            p += stride;
            acc0 += v.x * w.x + v.y * w.y;
            acc1 += v.z * w.z + v.w * w.w;
        }
    }
    float acc = acc0 + acc1;

    __shared__ float wsum[8];
    #pragma unroll
    for (int o = 16; o; o >>= 1) acc += __shfl_xor_sync(0xffffffffu, acc, o);
    if ((t & 31) == 0) wsum[t >> 5] = acc;
    __syncthreads();
    if (t < 8) {
        float v = wsum[t];
        #pragma unroll
        for (int o = 4; o; o >>= 1) v += __shfl_xor_sync(0xffu, v, o);
        if (t == 0) { d_part[blk] = v; __threadfence(); }
    }
    __syncthreads();
    cudaTriggerProgrammaticLaunchCompletion();   // release mlp at last store
}

// ---- Kernel 2: fold partials + tiny MLP + sigmoid (PDL) ----------------------
__global__ __launch_bounds__(256) void mlp_kernel(const float* __restrict__ w1,
                                                  const float* __restrict__ w2) {
    __shared__ float sg[1024];
    __shared__ float sw1[32][129];   // padded: conflict-free column reads
    __shared__ float sw2[128][33];
    __shared__ float st1[256];
    int tid = threadIdx.x;

    // Independent of d_part: overlaps reduce_kernel execution.
    for (int i = tid; i < 4096; i += 256) {
        sw1[i >> 7][i & 127] = w1[i];   // w1[j][c], j<32, c<128
        sw2[i >> 5][i & 31]  = w2[i];   // w2[c][j], c<128, j<32
    }

    cudaGridDependencySynchronize();    // wait for reduce_kernel's d_part

    for (int i = tid; i < 1024; i += 256) {
        const float* p = &d_part[i * BLKS_PER_CH];
        sg[i] = ((p[0] + p[1]) + (p[2] + p[3])) + p[4];
    }
    __syncthreads();

    // Stage 1: t1[b][j] = sum_c gap[b][c] * w1[j][c]
    int b = tid >> 5, j = tid & 31;
    float sacc = 0.f;
    #pragma unroll 8
    for (int c = 0; c < 128; c++) sacc += sg[b * 128 + c] * sw1[j][c];
    st1[tid] = sacc;
    __syncthreads();

    // Stage 2: att[b][c] = sigmoid(sum_j t1[b][j] * w2[c][j])
    for (int i = tid; i < 1024; i += 256) {
        int bb = i >> 7, cc = i & 127;
        float z = 0.f;
        #pragma unroll
        for (int jj = 0; jj < 32; jj++) z += st1[bb * 32 + jj] * sw2[cc][jj];
        d_att[i] = 1.f / (1.f + expf(-z));
    }
    __threadfence();
    __syncthreads();
    cudaTriggerProgrammaticLaunchCompletion();   // release scale at d_att store
}

// ---- Kernel 3: scale, 4 float4/thread, exact flat grid (PDL) -----------------
__global__ __launch_bounds__(256) void scale_kernel(const float4* __restrict__ x,
                                                    float4* __restrict__ out) {
    unsigned i0 = blockIdx.x * 1024u + threadIdx.x;   // block spans 1024 float4
    unsigned i1 = i0 + 256u;
    unsigned i2 = i0 + 512u;
    unsigned i3 = i0 + 768u;
    // All loads issue before the sync — front-batched, hides the mlp bubble.
    float4 v0 = __ldcs(&x[i0]);
    float4 v1 = __ldcs(&x[i1]);
    float4 v2 = __ldcs(&x[i2]);
    float4 v3 = __ldcs(&x[i3]);
    unsigned ch0 = i0 / (unsigned)Q_PER_CH;
    unsigned ch1 = i1 / (unsigned)Q_PER_CH;
    unsigned ch2 = i2 / (unsigned)Q_PER_CH;
    unsigned ch3 = i3 / (unsigned)Q_PER_CH;

    cudaGridDependencySynchronize();     // wait only for d_att

    float a0 = d_att[ch0], a1 = d_att[ch1], a2 = d_att[ch2], a3 = d_att[ch3];
    v0.x *= a0; v0.y *= a0; v0.z *= a0; v0.w *= a0;
    v1.x *= a1; v1.y *= a1; v1.z *= a1; v1.w *= a1;
    v2.x *= a2; v2.y *= a2; v2.z *= a2; v2.w *= a2;
    v3.x *= a3; v3.y *= a3; v3.z *= a3; v3.w *= a3;
    __stcs(&out[i0], v0);
    __stcs(&out[i1], v1);
    __stcs(&out[i2], v2);
    __stcs(&out[i3], v3);
}

// ---- Launch ------------------------------------------------------------------
extern "C" void kernel_launch(void* const* d_in, const int* in_sizes, int n_in,
                              void* d_out, int out_size) {
    const float* x  = (const float*)d_in[0];
    const float* w1 = (const float*)d_in[1];
    const float* w2 = (const float*)d_in[2];
    float* out = (float*)d_out;

    reduce_kernel<<<N_CH * BLKS_PER_CH, 256>>>(reinterpret_cast<const float4*>(x));

    cudaLaunchAttribute attr[1];
    attr[0].id = cudaLaunchAttributeProgrammaticStreamSerialization;
    attr[0].val.programmaticStreamSerializationAllowed = 1;

    {   // mlp: PDL-overlapped with reduce
        cudaLaunchConfig_t cfg = {};
        cfg.gridDim = dim3(1, 1, 1);
        cfg.blockDim = dim3(256, 1, 1);
        cfg.dynamicSmemBytes = 0;
        cfg.stream = 0;
        cfg.attrs = attr;
        cfg.numAttrs = 1;
        cudaLaunchKernelEx(&cfg, mlp_kernel, w1, w2);
    }
    {   // scale: PDL-overlapped with mlp
        cudaLaunchConfig_t cfg = {};
        cfg.gridDim = dim3(TOTAL_Q4 / 1024, 1, 1);    // 24000 blocks, no tail
        cfg.blockDim = dim3(256, 1, 1);
        cfg.dynamicSmemBytes = 0;
        cfg.stream = 0;
        cfg.attrs = attr;
        cfg.numAttrs = 1;
        cudaLaunchKernelEx(&cfg, scale_kernel,
                           reinterpret_cast<const float4*>(x),
                           reinterpret_cast<float4*>(out));
    }
}

// round 15
// speedup vs baseline: 1.0099x; 1.0099x over previous
#include <cuda_runtime.h>
#include <math.h>

// ---------------------------------------------------------------------------
// BalancedFrequencyAttention, collapsed form (see R2 derivation):
//   gap[b,c] = sum_{h,n} x[b,c,h,n] * w(h,n)
//   w(h,n)   = c0 + [h>=80] * (0.4/48000) * g_{(h-80)%3}(n),  period-12 in n
//   att      = sigmoid(gap @ w1^T @ w2^T);  out = x * att[:,:,None,None]
//
// R12 = best-measured R9 configuration (strided reduce, 2 float4/thread
// exact-flat scale, PDL + early triggers) with the MLP parallelized across
// 8 blocks (one per batch): per-batch fold/stage1/stage2 are independent,
// each block preloads w1/w2 pre-sync (overlapped with reduce).
// ---------------------------------------------------------------------------

#define N_CH        1024      // B*C
#define Q_PER_CH    24000     // 200*480/4 float4 per channel
#define BLKS_PER_CH 5
#define TOTAL_Q4    (N_CH * Q_PER_CH)        // 24,576,000 = 48000 * 512

__device__ float d_part[N_CH * BLKS_PER_CH];
__device__ float d_att[N_CH];

// ---- Kernel 1: weighted reduction, constant-register weights (R8 form) -------
__global__ __launch_bounds__(256, 8) void reduce_kernel(const float4* __restrict__ x) {
    const float c0  = 8.838834764831843e-06f;   // 0.6/sqrt(2)/48000
    const float inv = 8.333333333333334e-06f;   // 0.4/48000
    const float PI  = 3.14159265358979323846f;

    const int blk = blockIdx.x;
    const int ch  = blk / BLKS_PER_CH;
    const int s   = blk - ch * BLKS_PER_CH;

    const int t    = threadIdx.x;
    const int c4   = t & 127;          // float4 column (0..119 active)
    const int r    = t >> 7;           // row-within-pair (0/1)
    const bool act = (c4 < 120);

    // Per-thread constant weight (computed once).
    float4 w = make_float4(c0, c0, c0, c0);
    if (s >= 2) {
        const int k  = s - 2;
        const int n0 = c4 << 2;
        float g[4];
        #pragma unroll
        for (int e = 0; e < 4; e++) {
            float a = (float)(2 * ((n0 + e) % 12) + 1);
            float gv;
            if (k == 0)      gv = cosf(a * (PI / 12.f)) + cosf(a * (PI / 3.f));
            else if (k == 1) gv = cosf(a * (PI / 6.f))  + cosf(a * (5.f * PI / 12.f));
            else             gv = cosf(a * (PI / 4.f));
            g[e] = c0 + inv * gv;
        }
        w = make_float4(g[0], g[1], g[2], g[3]);
    }

    size_t base; int stride;
    if (s < 2) {                           // low: contiguous rows 40s .. 40s+39
        base   = (size_t)ch * Q_PER_CH + (size_t)(40 * s + r) * 120 + c4;
        stride = 240;                      // 2 rows
    } else {                               // high class k: rows 80+k+3m
        base   = (size_t)ch * Q_PER_CH + (size_t)(80 + (s - 2) + 3 * r) * 120 + c4;
        stride = 720;                      // 2 strided rows (6 physical rows)
    }

    float acc0 = 0.f, acc1 = 0.f;
    if (act) {
        const float4* p = x + base;
        #pragma unroll 5
        for (int i = 0; i < 20; i++) {
            float4 v = __ldcs(p);
            p += stride;
            acc0 += v.x * w.x + v.y * w.y;
            acc1 += v.z * w.z + v.w * w.w;
        }
    }
    float acc = acc0 + acc1;

    __shared__ float wsum[8];
    #pragma unroll
    for (int o = 16; o; o >>= 1) acc += __shfl_xor_sync(0xffffffffu, acc, o);
    if ((t & 31) == 0) wsum[t >> 5] = acc;
    __syncthreads();
    if (t < 8) {
        float v = wsum[t];
        #pragma unroll
        for (int o = 4; o; o >>= 1) v += __shfl_xor_sync(0xffu, v, o);
        if (t == 0) { d_part[blk] = v; __threadfence(); }
    }
    __syncthreads();
    cudaTriggerProgrammaticLaunchCompletion();   // release mlp at last store
}

// ---- Kernel 2: MLP, one block per batch b (8 blocks, PDL) --------------------
__global__ __launch_bounds__(256) void mlp_kernel(const float* __restrict__ w1,
                                                  const float* __restrict__ w2) {
    __shared__ float sg[128];        // gap for this batch
    __shared__ float sw1[32][129];   // padded: conflict-free column reads
    __shared__ float sw2[128][33];
    __shared__ float st1[32];
    const int tid = threadIdx.x;
    const int b   = blockIdx.x;      // batch index, 0..7

    // Independent of d_part: overlaps reduce_kernel execution.
    for (int i = tid; i < 4096; i += 256) {
        sw1[i >> 7][i & 127] = w1[i];   // w1[j][c], j<32, c<128
        sw2[i >> 5][i & 31]  = w2[i];   // w2[c][j], c<128, j<32
    }

    cudaGridDependencySynchronize();    // wait for reduce_kernel's d_part

    // Fold partials for this batch's 128 channels (640 floats from L2).
    if (tid < 128) {
        const float* p = &d_part[(b * 128 + tid) * BLKS_PER_CH];
        sg[tid] = ((p[0] + p[1]) + (p[2] + p[3])) + p[4];
    }
    __syncthreads();

    // Stage 1: t1[j] = sum_c gap[c] * w1[j][c]  — 8 threads per j, 16 c each.
    {
        int j = tid >> 3, part = tid & 7;     // j<32, part<8
        float s = 0.f;
        #pragma unroll
        for (int c = part * 16; c < part * 16 + 16; c++) s += sg[c] * sw1[j][c];
        #pragma unroll
        for (int o = 4; o; o >>= 1) s += __shfl_xor_sync(0xffffffffu, s, o);
        if (part == 0) st1[j] = s;
    }
    __syncthreads();

    // Stage 2: att[c] = sigmoid(sum_j t1[j] * w2[c][j])  — threads 0..127.
    if (tid < 128) {
        float z = 0.f;
        #pragma unroll
        for (int jj = 0; jj < 32; jj++) z += st1[jj] * sw2[tid][jj];
        d_att[b * 128 + tid] = 1.f / (1.f + expf(-z));
    }
    __threadfence();
    __syncthreads();
    cudaTriggerProgrammaticLaunchCompletion();   // release scale at d_att store
}

// ---- Kernel 3: scale, 2 float4/thread, exact flat grid (PDL) -----------------
__global__ __launch_bounds__(256) void scale_kernel(const float4* __restrict__ x,
                                                    float4* __restrict__ out) {
    unsigned i0 = blockIdx.x * 512u + threadIdx.x;    // < 24,576,000 always
    unsigned i1 = i0 + 256u;
    float4 v0 = __ldcs(&x[i0]);          // both loads issue before the sync
    float4 v1 = __ldcs(&x[i1]);
    unsigned c0 = i0 / (unsigned)Q_PER_CH;
    unsigned c1 = i1 / (unsigned)Q_PER_CH;

    cudaGridDependencySynchronize();     // wait only for d_att

    float a0 = d_att[c0];
    float a1 = d_att[c1];
    v0.x *= a0; v0.y *= a0; v0.z *= a0; v0.w *= a0;
    v1.x *= a1; v1.y *= a1; v1.z *= a1; v1.w *= a1;
    __stcs(&out[i0], v0);
    __stcs(&out[i1], v1);
}

// ---- Launch ------------------------------------------------------------------
extern "C" void kernel_launch(void* const* d_in, const int* in_sizes, int n_in,
                              void* d_out, int out_size) {
    const float* x  = (const float*)d_in[0];
    const float* w1 = (const float*)d_in[1];
    const float* w2 = (const float*)d_in[2];
    float* out = (float*)d_out;

    reduce_kernel<<<N_CH * BLKS_PER_CH, 256>>>(reinterpret_cast<const float4*>(x));

    cudaLaunchAttribute attr[1];
    attr[0].id = cudaLaunchAttributeProgrammaticStreamSerialization;
    attr[0].val.programmaticStreamSerializationAllowed = 1;

    {   // mlp: 8 blocks (one per batch), PDL-overlapped with reduce
        cudaLaunchConfig_t cfg = {};
        cfg.gridDim = dim3(8, 1, 1);
        cfg.blockDim = dim3(256, 1, 1);
        cfg.dynamicSmemBytes = 0;
        cfg.stream = 0;
        cfg.attrs = attr;
        cfg.numAttrs = 1;
        cudaLaunchKernelEx(&cfg, mlp_kernel, w1, w2);
    }
    {   // scale: PDL-overlapped with mlp
        cudaLaunchConfig_t cfg = {};
        cfg.gridDim = dim3(TOTAL_Q4 / 512, 1, 1);     // 48000 blocks, no tail
        cfg.blockDim = dim3(256, 1, 1);
        cfg.dynamicSmemBytes = 0;
        cfg.stream = 0;
        cfg.attrs = attr;
        cfg.numAttrs = 1;
        cudaLaunchKernelEx(&cfg, scale_kernel,
                           reinterpret_cast<const float4*>(x),
                           reinterpret_cast<float4*>(out));
    }
}

// round 16
// speedup vs baseline: 1.0336x; 1.0235x over previous
#include <cuda_runtime.h>
#include <math.h>

// ---------------------------------------------------------------------------
// BalancedFrequencyAttention, collapsed form (see R2 derivation):
//   gap[b,c] = sum_{h,n} x[b,c,h,n] * w(h,n)
//   w(h,n)   = c0 + [h>=80] * (0.4/48000) * g_{(h-80)%3}(n),  period-12 in n
//   att      = sigmoid(gap @ w1^T @ w2^T);  out = x * att[:,:,None,None]
//
// R15 = R12 best config with reduce split 5 -> 10 blocks/channel (20-row
// units) to halve the partial-wave tail. Access pattern per block is
// unchanged in character: constant-register weights, strides 240/720,
// LDG.128 + 4 FFMA inner loop. mlp folds 10 partials. Scale + PDL chain
// frozen at best-measured form.
// ---------------------------------------------------------------------------

#define N_CH        1024      // B*C
#define Q_PER_CH    24000     // 200*480/4 float4 per channel
#define BLKS_PER_CH 10
#define TOTAL_Q4    (N_CH * Q_PER_CH)        // 24,576,000 = 48000 * 512

__device__ float d_part[N_CH * BLKS_PER_CH];
__device__ float d_att[N_CH];

// ---- Kernel 1: weighted reduction, constant-register weights, 20-row units ---
__global__ __launch_bounds__(256, 8) void reduce_kernel(const float4* __restrict__ x) {
    const float c0  = 8.838834764831843e-06f;   // 0.6/sqrt(2)/48000
    const float inv = 8.333333333333334e-06f;   // 0.4/48000
    const float PI  = 3.14159265358979323846f;

    const int blk = blockIdx.x;
    const int ch  = blk / BLKS_PER_CH;
    const int s   = blk - ch * BLKS_PER_CH;

    const int t    = threadIdx.x;
    const int c4   = t & 127;          // float4 column (0..119 active)
    const int r    = t >> 7;           // row-within-pair (0/1)
    const bool act = (c4 < 120);

    // Per-thread constant weight (computed once).
    float4 w = make_float4(c0, c0, c0, c0);
    if (s >= 4) {
        const int k  = (s - 4) % 3;    // high class (h-80)%3 == k, fixed
        const int n0 = c4 << 2;
        float g[4];
        #pragma unroll
        for (int e = 0; e < 4; e++) {
            float a = (float)(2 * ((n0 + e) % 12) + 1);
            float gv;
            if (k == 0)      gv = cosf(a * (PI / 12.f)) + cosf(a * (PI / 3.f));
            else if (k == 1) gv = cosf(a * (PI / 6.f))  + cosf(a * (5.f * PI / 12.f));
            else             gv = cosf(a * (PI / 4.f));
            g[e] = c0 + inv * gv;
        }
        w = make_float4(g[0], g[1], g[2], g[3]);
    }

    size_t base; int stride;
    if (s < 4) {                           // low: contiguous rows 20s .. 20s+19
        base   = (size_t)ch * Q_PER_CH + (size_t)(20 * s + r) * 120 + c4;
        stride = 240;                      // 2 rows per iteration
    } else {                               // high: class k, m-half half
        const int k    = (s - 4) % 3;
        const int half = (s - 4) / 3;      // m in [20*half, 20*half+20)
        base   = (size_t)ch * Q_PER_CH
               + (size_t)(80 + k + 60 * half + 3 * r) * 120 + c4;
        stride = 720;                      // 2 strided rows (6 physical rows)
    }

    float acc0 = 0.f, acc1 = 0.f;
    if (act) {
        const float4* p = x + base;
        #pragma unroll 5
        for (int i = 0; i < 10; i++) {     // 20 rows per block (2 per iter)
            float4 v = __ldcs(p);
            p += stride;
            acc0 += v.x * w.x + v.y * w.y;
            acc1 += v.z * w.z + v.w * w.w;
        }
    }
    float acc = acc0 + acc1;

    __shared__ float wsum[8];
    #pragma unroll
    for (int o = 16; o; o >>= 1) acc += __shfl_xor_sync(0xffffffffu, acc, o);
    if ((t & 31) == 0) wsum[t >> 5] = acc;
    __syncthreads();
    if (t < 8) {
        float v = wsum[t];
        #pragma unroll
        for (int o = 4; o; o >>= 1) v += __shfl_xor_sync(0xffu, v, o);
        if (t == 0) { d_part[blk] = v; __threadfence(); }
    }
    __syncthreads();
    cudaTriggerProgrammaticLaunchCompletion();   // release mlp at last store
}

// ---- Kernel 2: MLP, one block per batch b (8 blocks, PDL) --------------------
__global__ __launch_bounds__(256) void mlp_kernel(const float* __restrict__ w1,
                                                  const float* __restrict__ w2) {
    __shared__ float sg[128];        // gap for this batch
    __shared__ float sw1[32][129];   // padded: conflict-free column reads
    __shared__ float sw2[128][33];
    __shared__ float st1[32];
    const int tid = threadIdx.x;
    const int b   = blockIdx.x;      // batch index, 0..7

    // Independent of d_part: overlaps reduce_kernel execution.
    for (int i = tid; i < 4096; i += 256) {
        sw1[i >> 7][i & 127] = w1[i];   // w1[j][c], j<32, c<128
        sw2[i >> 5][i & 31]  = w2[i];   // w2[c][j], c<128, j<32
    }

    cudaGridDependencySynchronize();    // wait for reduce_kernel's d_part

    // Fold 10 partials for this batch's 128 channels.
    if (tid < 128) {
        const float* p = &d_part[(b * 128 + tid) * BLKS_PER_CH];
        float v = 0.f;
        #pragma unroll
        for (int q = 0; q < BLKS_PER_CH; q++) v += p[q];
        sg[tid] = v;
    }
    __syncthreads();

    // Stage 1: t1[j] = sum_c gap[c] * w1[j][c]  — 8 threads per j, 16 c each.
    {
        int j = tid >> 3, part = tid & 7;     // j<32, part<8
        float s = 0.f;
        #pragma unroll
        for (int c = part * 16; c < part * 16 + 16; c++) s += sg[c] * sw1[j][c];
        #pragma unroll
        for (int o = 4; o; o >>= 1) s += __shfl_xor_sync(0xffffffffu, s, o);
        if (part == 0) st1[j] = s;
    }
    __syncthreads();

    // Stage 2: att[c] = sigmoid(sum_j t1[j] * w2[c][j])  — threads 0..127.
    if (tid < 128) {
        float z = 0.f;
        #pragma unroll
        for (int jj = 0; jj < 32; jj++) z += st1[jj] * sw2[tid][jj];
        d_att[b * 128 + tid] = 1.f / (1.f + expf(-z));
    }
    __threadfence();
    __syncthreads();
    cudaTriggerProgrammaticLaunchCompletion();   // release scale at d_att store
}

// ---- Kernel 3: scale, 2 float4/thread, exact flat grid (PDL) -----------------
__global__ __launch_bounds__(256) void scale_kernel(const float4* __restrict__ x,
                                                    float4* __restrict__ out) {
    unsigned i0 = blockIdx.x * 512u + threadIdx.x;    // < 24,576,000 always
    unsigned i1 = i0 + 256u;
    float4 v0 = __ldcs(&x[i0]);          // both loads issue before the sync
    float4 v1 = __ldcs(&x[i1]);
    unsigned c0 = i0 / (unsigned)Q_PER_CH;
    unsigned c1 = i1 / (unsigned)Q_PER_CH;

    cudaGridDependencySynchronize();     // wait only for d_att

    float a0 = d_att[c0];
    float a1 = d_att[c1];
    v0.x *= a0; v0.y *= a0; v0.z *= a0; v0.w *= a0;
    v1.x *= a1; v1.y *= a1; v1.z *= a1; v1.w *= a1;
    __stcs(&out[i0], v0);
    __stcs(&out[i1], v1);
}

// ---- Launch ------------------------------------------------------------------
extern "C" void kernel_launch(void* const* d_in, const int* in_sizes, int n_in,
                              void* d_out, int out_size) {
    const float* x  = (const float*)d_in[0];
    const float* w1 = (const float*)d_in[1];
    const float* w2 = (const float*)d_in[2];
    float* out = (float*)d_out;

    reduce_kernel<<<N_CH * BLKS_PER_CH, 256>>>(reinterpret_cast<const float4*>(x));

    cudaLaunchAttribute attr[1];
    attr[0].id = cudaLaunchAttributeProgrammaticStreamSerialization;
    attr[0].val.programmaticStreamSerializationAllowed = 1;

    {   // mlp: 8 blocks (one per batch), PDL-overlapped with reduce
        cudaLaunchConfig_t cfg = {};
        cfg.gridDim = dim3(8, 1, 1);
        cfg.blockDim = dim3(256, 1, 1);
        cfg.dynamicSmemBytes = 0;
        cfg.stream = 0;
        cfg.attrs = attr;
        cfg.numAttrs = 1;
        cudaLaunchKernelEx(&cfg, mlp_kernel, w1, w2);
    }
    {   // scale: PDL-overlapped with mlp
        cudaLaunchConfig_t cfg = {};
        cfg.gridDim = dim3(TOTAL_Q4 / 512, 1, 1);     // 48000 blocks, no tail
        cfg.blockDim = dim3(256, 1, 1);
        cfg.dynamicSmemBytes = 0;
        cfg.stream = 0;
        cfg.attrs = attr;
        cfg.numAttrs = 1;
        cudaLaunchKernelEx(&cfg, scale_kernel,
                           reinterpret_cast<const float4*>(x),
                           reinterpret_cast<float4*>(out));
    }
}